// round 1
// baseline (speedup 1.0000x reference)
#include <cuda_runtime.h>
#include <cstdint>

// ---------------- problem constants ----------------
#define HV 128
#define HT 17
#define KTYPES 8
#define DIM 290            // 2*(HV+HT)
#define DPAD 296           // padded to multiple of 8 (BK)
#define OGATES 640         // 5*HV
#define NP 400000
#define NN 200000

#define BM 128
#define BN 128
#define BK 8
#define MAXTILES 1571              // ceil over worst-case per-type padding
#define MAXROWS (MAXTILES * BM)    // 201088

// ---------------- device scratch (static, no allocation) ----------------
__device__ int   g_cnt[KTYPES];
__device__ int   g_off[KTYPES + 1];
__device__ int   g_fill[KTYPES];
__device__ int   g_ntiles;
__device__ int   g_tile_type[MAXTILES];
__device__ int   g_perm[MAXROWS];     // row -> node (-1 for pad rows)
__device__ int   g_rowof[NN];         // node -> row
__device__ float g_Wp[KTYPES * OGATES * DPAD];           // ~6.1 MB
__device__ float g_X[(size_t)MAXROWS * DPAD];            // ~238 MB
__device__ float g_G[(size_t)MAXROWS * OGATES];          // ~515 MB

// ---------------- stage 0: init ----------------
__global__ void k_init() {
    int i = blockIdx.x * blockDim.x + threadIdx.x;
    if (i < MAXROWS) g_perm[i] = -1;
    if (i < KTYPES) g_cnt[i] = 0;
}

__global__ void k_hist(const int* __restrict__ parent_type) {
    int i = blockIdx.x * blockDim.x + threadIdx.x;
    if (i < NN) atomicAdd(&g_cnt[parent_type[i]], 1);
}

__global__ void k_offsets() {
    // single thread
    int off = 0;
    for (int k = 0; k < KTYPES; k++) {
        g_off[k] = off;
        g_fill[k] = off;
        int tiles = (g_cnt[k] + BM - 1) / BM;
        for (int t = 0; t < tiles; t++) g_tile_type[off / BM + t] = k;
        off += tiles * BM;
    }
    g_off[KTYPES] = off;
    g_ntiles = off / BM;
}

__global__ void k_scatter(const int* __restrict__ parent_type) {
    int i = blockIdx.x * blockDim.x + threadIdx.x;
    if (i < NN) {
        int k = parent_type[i];
        int pos = atomicAdd(&g_fill[k], 1);
        g_perm[pos] = i;
        g_rowof[i] = pos;
    }
}

// ---------------- stage 1: pad W into [k][o][DPAD] ----------------
__global__ void k_padW(const float* __restrict__ W) {
    int idx = blockIdx.x * blockDim.x + threadIdx.x;
    if (idx >= KTYPES * OGATES * DPAD) return;
    int og = idx / DPAD;       // k*OGATES + o
    int d  = idx % DPAD;
    g_Wp[idx] = (d < DIM) ? W[(size_t)og * DIM + d] : 0.f;
}

// ---------------- stage 2: gather X rows ----------------
__global__ void k_gather(const float* __restrict__ h_pool,
                         const float* __restrict__ t_pool,
                         const int* __restrict__ child_idx) {
    int row = blockIdx.x;
    float* xr = g_X + (size_t)row * DPAD;
    int node = (row < g_off[KTYPES]) ? g_perm[row] : -1;
    if (node < 0) {
        for (int j = threadIdx.x; j < DPAD; j += blockDim.x) xr[j] = 0.f;
        return;
    }
    int li = child_idx[2 * node];
    int ri = child_idx[2 * node + 1];
    const float* hl = h_pool + (size_t)li * HV;
    const float* hr = h_pool + (size_t)ri * HV;
    const float* tl = t_pool + (size_t)li * HT;
    const float* tr = t_pool + (size_t)ri * HT;
    for (int j = threadIdx.x; j < DPAD; j += blockDim.x) {
        float v;
        if (j < HV)                 v = hl[j];
        else if (j < HV + HT)       v = tl[j - HV];
        else if (j < 2 * HV + HT)   v = hr[j - (HV + HT)];
        else if (j < DIM)           v = tr[j - (2 * HV + HT)];
        else                        v = 0.f;
        xr[j] = v;
    }
}

// ---------------- stage 3: grouped SGEMM  G[row][o] = X[row] . Wp[type][o] ----------------
__global__ void __launch_bounds__(256) k_gemm() {
    int tile = blockIdx.x;
    if (tile >= g_ntiles) return;
    int typ  = g_tile_type[tile];
    int row0 = tile * BM;
    int col0 = blockIdx.y * BN;

    const float* Wbase = g_Wp + (size_t)typ * OGATES * DPAD;

    __shared__ float As[BK][BM];
    __shared__ float Bs[BK][BN];

    int t  = threadIdx.x;
    int lr = t >> 1;            // 0..127 : row (A) / gate (B) within tile
    int lc = (t & 1) * 4;       // 0 or 4 within BK chunk
    int tx = t % 16;
    int ty = t / 16;

    float acc[8][8];
#pragma unroll
    for (int i = 0; i < 8; i++)
#pragma unroll
        for (int j = 0; j < 8; j++) acc[i][j] = 0.f;

    const float* aptr = g_X + (size_t)(row0 + lr) * DPAD + lc;
    const float* bptr = Wbase + (size_t)(col0 + lr) * DPAD + lc;

    for (int kc = 0; kc < DPAD; kc += BK) {
        float4 av = *(const float4*)(aptr + kc);
        float4 bv = *(const float4*)(bptr + kc);
        __syncthreads();
        As[lc + 0][lr] = av.x; As[lc + 1][lr] = av.y;
        As[lc + 2][lr] = av.z; As[lc + 3][lr] = av.w;
        Bs[lc + 0][lr] = bv.x; Bs[lc + 1][lr] = bv.y;
        Bs[lc + 2][lr] = bv.z; Bs[lc + 3][lr] = bv.w;
        __syncthreads();
#pragma unroll
        for (int kk = 0; kk < BK; kk++) {
            float a[8], b[8];
            float4 a0 = *(const float4*)&As[kk][ty * 4];
            float4 a1 = *(const float4*)&As[kk][64 + ty * 4];
            float4 b0 = *(const float4*)&Bs[kk][tx * 4];
            float4 b1 = *(const float4*)&Bs[kk][64 + tx * 4];
            a[0] = a0.x; a[1] = a0.y; a[2] = a0.z; a[3] = a0.w;
            a[4] = a1.x; a[5] = a1.y; a[6] = a1.z; a[7] = a1.w;
            b[0] = b0.x; b[1] = b0.y; b[2] = b0.z; b[3] = b0.w;
            b[4] = b1.x; b[5] = b1.y; b[6] = b1.z; b[7] = b1.w;
#pragma unroll
            for (int i = 0; i < 8; i++)
#pragma unroll
                for (int j = 0; j < 8; j++)
                    acc[i][j] += a[i] * b[j];
        }
    }

    // store 8x8 micro-tile (rows ty*4..+3 and 64+ty*4..+3; cols tx*4..+3 and 64+tx*4..+3)
#pragma unroll
    for (int i = 0; i < 8; i++) {
        int r = row0 + ((i < 4) ? (ty * 4 + i) : (64 + ty * 4 + (i - 4)));
        float* grow = g_G + (size_t)r * OGATES + col0;
        float4 v0 = make_float4(acc[i][0], acc[i][1], acc[i][2], acc[i][3]);
        float4 v1 = make_float4(acc[i][4], acc[i][5], acc[i][6], acc[i][7]);
        *(float4*)(grow + tx * 4)      = v0;
        *(float4*)(grow + 64 + tx * 4) = v1;
    }
}

// ---------------- stage 4: LSTM epilogue ----------------
__device__ __forceinline__ float sigm(float x) { return 1.f / (1.f + expf(-x)); }

__global__ void k_epilogue(const float* __restrict__ c_pool,
                           const int* __restrict__ child_idx,
                           const int* __restrict__ parent_type,
                           const float* __restrict__ b,
                           float* __restrict__ out) {
    int n = blockIdx.x;
    int j = threadIdx.x;           // 0..127
    int row = g_rowof[n];
    int k = parent_type[n];
    const float* g  = g_G + (size_t)row * OGATES;
    const float* bk = b + (size_t)k * OGATES;

    float gi  = g[j]       + bk[j];
    float gfl = g[128 + j] + bk[128 + j];
    float gfr = g[256 + j] + bk[256 + j];
    float gu  = g[384 + j] + bk[384 + j];
    float go  = g[512 + j] + bk[512 + j];

    int li = child_idx[2 * n];
    int ri = child_idx[2 * n + 1];
    float cl = c_pool[(size_t)li * HV + j];
    float cr = c_pool[(size_t)ri * HV + j];

    float c = sigm(gi) * tanhf(gu) + sigm(gfl) * cl + sigm(gfr) * cr;
    float h = sigm(go) * tanhf(c);

    out[(size_t)n * 256 + j]       = h;
    out[(size_t)n * 256 + 128 + j] = c;
}

// ---------------- launch ----------------
extern "C" void kernel_launch(void* const* d_in, const int* in_sizes, int n_in,
                              void* d_out, int out_size) {
    const float* h_pool      = (const float*)d_in[0];
    const float* c_pool      = (const float*)d_in[1];
    const float* t_pool      = (const float*)d_in[2];
    const int*   child_idx   = (const int*)d_in[3];
    const int*   parent_type = (const int*)d_in[4];
    const float* W           = (const float*)d_in[5];
    const float* b           = (const float*)d_in[6];
    float* out = (float*)d_out;

    k_init<<<(MAXROWS + 255) / 256, 256>>>();
    k_hist<<<(NN + 255) / 256, 256>>>(parent_type);
    k_offsets<<<1, 1>>>();
    k_scatter<<<(NN + 255) / 256, 256>>>(parent_type);
    k_padW<<<(KTYPES * OGATES * DPAD + 255) / 256, 256>>>(W);
    k_gather<<<MAXROWS, 128>>>(h_pool, t_pool, child_idx);
    dim3 ggrid(MAXTILES, OGATES / BN);
    k_gemm<<<ggrid, 256>>>();
    k_epilogue<<<NN, 128>>>(c_pool, child_idx, parent_type, b, out);
}

// round 4
// speedup vs baseline: 2.3903x; 2.3903x over previous
#include <cuda_runtime.h>
#include <cstdint>

// ---------------- problem constants ----------------
#define HV 128
#define HT 17
#define KTYPES 8
#define DIM 290            // 2*(HV+HT)
#define DPAD 320           // padded K, 10 chunks of 32
#define OGATES 640         // 5*HV
#define NN 200000
#define BM 128
#define BN 128
#define MAXTILES 1571
#define MAXROWS (MAXTILES*BM)

#define CHUNK_K 32
#define CS 36              // smem row stride (f32) -> conflict-free (4g+t) frag loads
#define CHUNK_F32 (128*CS) // one chunk buffer
#define SMBYTES (4*CHUNK_F32*4)   // A double + B double = 73728 B

// ---------------- device scratch ----------------
__device__ int   g_cnt[KTYPES];
__device__ int   g_off[KTYPES+1];
__device__ int   g_fill[KTYPES];
__device__ int   g_tile_type[MAXTILES];
__device__ int   g_perm[MAXROWS];                 // row -> node (-1 = pad)
__device__ int   g_rowof[NN];                     // node -> row
__device__ float g_Wp[KTYPES*OGATES*DPAD];        // padded, tf32-rounded weights
__device__ float g_X[(size_t)MAXROWS*DPAD];       // gathered, tf32-rounded inputs
__device__ float g_G[(size_t)MAXROWS*OGATES];     // gate pre-activations

// ---------------- helpers ----------------
__device__ __forceinline__ uint32_t smem_u32(const void* p) {
    uint32_t a;
    asm("{ .reg .u64 t; cvta.to.shared.u64 t, %1; cvt.u32.u64 %0, t; }" : "=r"(a) : "l"(p));
    return a;
}
__device__ __forceinline__ float to_tf32(float x) {
    float r;
    asm("cvt.rna.tf32.f32 %0, %1;" : "=f"(r) : "f"(x));
    return r;
}
__device__ __forceinline__ float sigm(float x) { return 1.f / (1.f + expf(-x)); }

#define CP_ASYNC16(dst, src) \
    asm volatile("cp.async.cg.shared.global [%0], [%1], 16;" :: "r"(dst), "l"(src))
#define CP_COMMIT() asm volatile("cp.async.commit_group;" ::: "memory")
#define CP_WAIT0()  asm volatile("cp.async.wait_group 0;" ::: "memory")

__device__ __forceinline__ void mma_tf32(float* c, const uint32_t* a, const uint32_t* b) {
    asm volatile(
        "mma.sync.aligned.m16n8k8.row.col.f32.tf32.tf32.f32 "
        "{%0,%1,%2,%3}, {%4,%5,%6,%7}, {%8,%9}, {%0,%1,%2,%3};"
        : "+f"(c[0]), "+f"(c[1]), "+f"(c[2]), "+f"(c[3])
        : "r"(a[0]), "r"(a[1]), "r"(a[2]), "r"(a[3]), "r"(b[0]), "r"(b[1]));
}

// ---------------- setup kernels ----------------
__global__ void k_init() {
    int i = blockIdx.x * blockDim.x + threadIdx.x;
    if (i < MAXROWS) g_perm[i] = -1;
    if (i < MAXTILES) g_tile_type[i] = 0;
    if (i < KTYPES) g_cnt[i] = 0;
}

__global__ void k_hist(const int* __restrict__ parent_type) {
    __shared__ int loc[KTYPES];
    int t = threadIdx.x;
    if (t < KTYPES) loc[t] = 0;
    __syncthreads();
    int i = blockIdx.x * blockDim.x + t;
    if (i < NN) atomicAdd(&loc[parent_type[i]], 1);
    __syncthreads();
    if (t < KTYPES && loc[t]) atomicAdd(&g_cnt[t], loc[t]);
}

__global__ void k_offsets() {
    int off = 0;
    for (int k = 0; k < KTYPES; k++) {
        g_off[k] = off;
        g_fill[k] = off;
        int tiles = (g_cnt[k] + BM - 1) / BM;
        for (int t = 0; t < tiles; t++) g_tile_type[off / BM + t] = k;
        off += tiles * BM;
    }
    g_off[KTYPES] = off;
}

__global__ void k_scatter(const int* __restrict__ parent_type) {
    __shared__ int loc[KTYPES];
    __shared__ int base[KTYPES];
    int t = threadIdx.x;
    if (t < KTYPES) loc[t] = 0;
    __syncthreads();
    int i = blockIdx.x * blockDim.x + t;
    int k = 0, my = 0;
    if (i < NN) {
        k = parent_type[i];
        my = atomicAdd(&loc[k], 1);
    }
    __syncthreads();
    if (t < KTYPES && loc[t]) base[t] = atomicAdd(&g_fill[t], loc[t]);
    __syncthreads();
    if (i < NN) {
        int pos = base[k] + my;
        g_perm[pos] = i;
        g_rowof[i] = pos;
    }
}

__global__ void k_padW(const float* __restrict__ W) {
    int idx = blockIdx.x * blockDim.x + threadIdx.x;
    if (idx >= KTYPES * OGATES * DPAD) return;
    int og = idx / DPAD;
    int d  = idx % DPAD;
    g_Wp[idx] = (d < DIM) ? to_tf32(W[(size_t)og * DIM + d]) : 0.f;
}

__global__ void k_gather(const float* __restrict__ h_pool,
                         const float* __restrict__ t_pool,
                         const int* __restrict__ child_idx) {
    int row = blockIdx.x;
    float* xr = g_X + (size_t)row * DPAD;
    int node = g_perm[row];
    if (node < 0) {
        for (int j = threadIdx.x; j < DPAD; j += blockDim.x) xr[j] = 0.f;
        return;
    }
    int li = child_idx[2 * node];
    int ri = child_idx[2 * node + 1];
    const float* hl = h_pool + (size_t)li * HV;
    const float* hr = h_pool + (size_t)ri * HV;
    const float* tl = t_pool + (size_t)li * HT;
    const float* tr = t_pool + (size_t)ri * HT;
    for (int j = threadIdx.x; j < DPAD; j += blockDim.x) {
        float v;
        if (j < HV)                 v = hl[j];
        else if (j < HV + HT)       v = tl[j - HV];
        else if (j < 2 * HV + HT)   v = hr[j - (HV + HT)];
        else if (j < DIM)           v = tr[j - (2 * HV + HT)];
        else                        v = 0.f;
        xr[j] = to_tf32(v);
    }
}

// ---------------- tf32 mma GEMM: G[row][gate*128+n] = X[row] . Wp[type][col] ----------------
__device__ __forceinline__ void load_chunk(const float* __restrict__ base,
                                           uint32_t sdst, int kc, int tid) {
#pragma unroll
    for (int i = 0; i < 4; i++) {
        int f = tid + i * 256;
        int r = f >> 3, c = f & 7;
        const float* src = base + (size_t)r * DPAD + kc * CHUNK_K + c * 4;
        CP_ASYNC16(sdst + (uint32_t)(r * CS + c * 4) * 4u, src);
    }
}

__global__ void __launch_bounds__(256, 2) k_gemm() {
    extern __shared__ float sm[];
    float* As = sm;                       // 2 chunks
    float* Bs = sm + 2 * CHUNK_F32;       // 2 chunks
    uint32_t sA = smem_u32(As);
    uint32_t sB = smem_u32(Bs);

    int tile = blockIdx.x;
    int gate = blockIdx.y;
    int typ  = g_tile_type[tile];
    int row0 = tile * BM;

    const float* Abase = g_X + (size_t)row0 * DPAD;
    const float* Bbase = g_Wp + ((size_t)typ * OGATES + gate * BN) * DPAD;

    int tid = threadIdx.x;
    int lane = tid & 31, wid = tid >> 5;
    int wm = wid & 3;          // warp row block: rows wm*32 .. +31
    int wn = wid >> 2;         // warp col block: cols wn*64 .. +63
    int g = lane >> 2, t = lane & 3;

    float acc[2][8][4];
#pragma unroll
    for (int mt = 0; mt < 2; mt++)
#pragma unroll
        for (int nt = 0; nt < 8; nt++)
#pragma unroll
            for (int e = 0; e < 4; e++) acc[mt][nt][e] = 0.f;

    // preload chunk 0
    load_chunk(Abase, sA, 0, tid);
    load_chunk(Bbase, sB, 0, tid);
    CP_COMMIT();
    CP_WAIT0();
    __syncthreads();

    for (int kc = 0; kc < 10; kc++) {
        int cur = kc & 1, nxt = cur ^ 1;
        if (kc < 9) {
            load_chunk(Abase, sA + (uint32_t)nxt * CHUNK_F32 * 4u, kc + 1, tid);
            load_chunk(Bbase, sB + (uint32_t)nxt * CHUNK_F32 * 4u, kc + 1, tid);
            CP_COMMIT();
        }
        const float* Ac = As + cur * CHUNK_F32;
        const float* Bc = Bs + cur * CHUNK_F32;
#pragma unroll
        for (int ks = 0; ks < 4; ks++) {
            int kk = ks * 8;
            uint32_t afr[2][4], bfr[8][2];
#pragma unroll
            for (int mt = 0; mt < 2; mt++) {
                int rb = wm * 32 + mt * 16;
                afr[mt][0] = __float_as_uint(Ac[(rb + g) * CS + kk + t]);
                afr[mt][1] = __float_as_uint(Ac[(rb + g + 8) * CS + kk + t]);
                afr[mt][2] = __float_as_uint(Ac[(rb + g) * CS + kk + t + 4]);
                afr[mt][3] = __float_as_uint(Ac[(rb + g + 8) * CS + kk + t + 4]);
            }
#pragma unroll
            for (int nt = 0; nt < 8; nt++) {
                int cb = wn * 64 + nt * 8;
                bfr[nt][0] = __float_as_uint(Bc[(cb + g) * CS + kk + t]);
                bfr[nt][1] = __float_as_uint(Bc[(cb + g) * CS + kk + t + 4]);
            }
#pragma unroll
            for (int mt = 0; mt < 2; mt++)
#pragma unroll
                for (int nt = 0; nt < 8; nt++)
                    mma_tf32(acc[mt][nt], afr[mt], bfr[nt]);
        }
        if (kc < 9) CP_WAIT0();
        __syncthreads();
    }

    // store: C[g..][t*2, t*2+1] per (mt, nt)
#pragma unroll
    for (int mt = 0; mt < 2; mt++) {
        int r_lo = row0 + wm * 32 + mt * 16 + g;
        int r_hi = r_lo + 8;
#pragma unroll
        for (int nt = 0; nt < 8; nt++) {
            int col = gate * BN + wn * 64 + nt * 8 + t * 2;
            *(float2*)(g_G + (size_t)r_lo * OGATES + col) =
                make_float2(acc[mt][nt][0], acc[mt][nt][1]);
            *(float2*)(g_G + (size_t)r_hi * OGATES + col) =
                make_float2(acc[mt][nt][2], acc[mt][nt][3]);
        }
    }
}

// ---------------- LSTM epilogue ----------------
__global__ void k_epilogue(const float* __restrict__ c_pool,
                           const int* __restrict__ child_idx,
                           const int* __restrict__ parent_type,
                           const float* __restrict__ b,
                           float* __restrict__ out) {
    int n = blockIdx.x;
    int j = threadIdx.x;           // 0..127
    int row = g_rowof[n];
    int k = parent_type[n];
    const float* g  = g_G + (size_t)row * OGATES;
    const float* bk = b + (size_t)k * OGATES;

    float gi  = g[j]       + bk[j];
    float gfl = g[128 + j] + bk[128 + j];
    float gfr = g[256 + j] + bk[256 + j];
    float gu  = g[384 + j] + bk[384 + j];
    float go  = g[512 + j] + bk[512 + j];

    int li = child_idx[2 * n];
    int ri = child_idx[2 * n + 1];
    float cl = c_pool[(size_t)li * HV + j];
    float cr = c_pool[(size_t)ri * HV + j];

    float c = sigm(gi) * tanhf(gu) + sigm(gfl) * cl + sigm(gfr) * cr;
    float h = sigm(go) * tanhf(c);

    out[(size_t)n * 256 + j]       = h;
    out[(size_t)n * 256 + 128 + j] = c;
}

// ---------------- launch ----------------
extern "C" void kernel_launch(void* const* d_in, const int* in_sizes, int n_in,
                              void* d_out, int out_size) {
    const float* h_pool      = (const float*)d_in[0];
    const float* c_pool      = (const float*)d_in[1];
    const float* t_pool      = (const float*)d_in[2];
    const int*   child_idx   = (const int*)d_in[3];
    const int*   parent_type = (const int*)d_in[4];
    const float* W           = (const float*)d_in[5];
    const float* b           = (const float*)d_in[6];
    float* out = (float*)d_out;

    cudaFuncSetAttribute(k_gemm, cudaFuncAttributeMaxDynamicSharedMemorySize, SMBYTES);

    k_init<<<(MAXROWS + 255) / 256, 256>>>();
    k_hist<<<(NN + 255) / 256, 256>>>(parent_type);
    k_offsets<<<1, 1>>>();
    k_scatter<<<(NN + 255) / 256, 256>>>(parent_type);
    k_padW<<<(KTYPES * OGATES * DPAD + 255) / 256, 256>>>(W);
    k_gather<<<MAXROWS, 128>>>(h_pool, t_pool, child_idx);
    dim3 ggrid(MAXTILES, OGATES / BN);
    k_gemm<<<ggrid, 256, SMBYTES>>>();
    k_epilogue<<<NN, 128>>>(c_pool, child_idx, parent_type, b, out);
}